// round 6
// baseline (speedup 1.0000x reference)
#include <cuda_runtime.h>
#include <math.h>
#include <stdint.h>

#define T_TOK 2048
#define HDIM  1024
#define FFND  4096
#define NE    8
#define NF2   8192   // 2*FFND
#define NPAIR (2*T_TOK)

// ---------------- scratch (static device globals; no allocation) ------------
// NOTE: never pass these as kernel args from host (host shadow != device ptr).
__device__ int   d_count[NE];
__device__ int   d_list[NE * T_TOK];
__device__ float d_wgt[NPAIR];
__device__ float d_xtf[(size_t)T_TOK * HDIM];    // x pre-rounded to tf32
__device__ float d_z[(size_t)NPAIR * NF2];       // [pair, 8192] g|u
__device__ float d_actbuf[(size_t)NPAIR * FFND]; // silu(g)*u, tf32-rounded
__device__ float d_y[(size_t)NPAIR * HDIM];

// ---------------------------------------------------------------------------
__global__ void zero_counts_kernel() {
    if (threadIdx.x < NE) d_count[threadIdx.x] = 0;
}

__device__ __forceinline__ uint32_t f2tf32(float f) {
    uint32_t r;
    asm("cvt.rna.tf32.f32 %0, %1;" : "=r"(r) : "f"(f));
    return r;
}

// One warp per token: router logits, top-2 softmax weights, expert compaction.
__global__ void router_kernel(const float* __restrict__ x,
                              const float* __restrict__ gw,
                              float* __restrict__ rlogits) {
    int gwarp = (blockIdx.x * blockDim.x + threadIdx.x) >> 5;
    int lane  = threadIdx.x & 31;
    if (gwarp >= T_TOK) return;
    const float* xr = x + (size_t)gwarp * HDIM;

    float acc[NE];
#pragma unroll
    for (int e = 0; e < NE; e++) acc[e] = 0.f;
    for (int h = lane; h < HDIM; h += 32) {
        float xv = xr[h];
#pragma unroll
        for (int e = 0; e < NE; e++) acc[e] += xv * gw[e * HDIM + h];
    }
#pragma unroll
    for (int e = 0; e < NE; e++)
#pragma unroll
        for (int off = 16; off; off >>= 1)
            acc[e] += __shfl_xor_sync(0xffffffffu, acc[e], off);

    if (lane == 0) {
#pragma unroll
        for (int e = 0; e < NE; e++) rlogits[gwarp * NE + e] = acc[e];
        int e0 = 0;
#pragma unroll
        for (int e = 1; e < NE; e++) if (acc[e] > acc[e0]) e0 = e;
        int e1 = (e0 == 0) ? 1 : 0;
#pragma unroll
        for (int e = 0; e < NE; e++)
            if (e != e0 && acc[e] > acc[e1]) e1 = e;
        float p1 = __expf(acc[e1] - acc[e0]);
        float inv = 1.0f / (1.0f + p1);
        d_wgt[gwarp * 2 + 0] = inv;
        d_wgt[gwarp * 2 + 1] = p1 * inv;

        int pos0 = atomicAdd(&d_count[e0], 1);
        d_list[e0 * T_TOK + pos0] = gwarp * 2 + 0;
        int pos1 = atomicAdd(&d_count[e1], 1);
        d_list[e1 * T_TOK + pos1] = gwarp * 2 + 1;
    }
}

// Pre-round x to tf32 bit patterns (A-side of GEMM1 then needs no cvt).
__global__ void convert_x_kernel(const float* __restrict__ x) {
    int i4 = blockIdx.x * blockDim.x + threadIdx.x;   // over T*H/4
    if (i4 >= T_TOK * HDIM / 4) return;
    float4 v = ((const float4*)x)[i4];
    uint4 u;
    u.x = f2tf32(v.x); u.y = f2tf32(v.y);
    u.z = f2tf32(v.z); u.w = f2tf32(v.w);
    ((uint4*)d_xtf)[i4] = u;
}

// ---------------- mma helpers ------------------------------------------------
__device__ __forceinline__ void mma_tf32(float* d, const uint32_t* a, const uint32_t* b) {
    asm volatile(
        "mma.sync.aligned.m16n8k8.row.col.f32.tf32.tf32.f32 "
        "{%0,%1,%2,%3}, {%4,%5,%6,%7}, {%8,%9}, {%0,%1,%2,%3};\n"
        : "+f"(d[0]), "+f"(d[1]), "+f"(d[2]), "+f"(d[3])
        : "r"(a[0]), "r"(a[1]), "r"(a[2]), "r"(a[3]), "r"(b[0]), "r"(b[1]));
}

__device__ __forceinline__ void ldsm_x4(uint32_t* r, uint32_t addr) {
    asm volatile("ldmatrix.sync.aligned.m8n8.x4.shared.b16 {%0,%1,%2,%3}, [%4];"
                 : "=r"(r[0]), "=r"(r[1]), "=r"(r[2]), "=r"(r[3]) : "r"(addr));
}
__device__ __forceinline__ void ldsm_x2(uint32_t* r, uint32_t addr) {
    asm volatile("ldmatrix.sync.aligned.m8n8.x2.shared.b16 {%0,%1}, [%2];"
                 : "=r"(r[0]), "=r"(r[1]) : "r"(addr));
}

__device__ __forceinline__ void cp16(uint32_t smem_dst, const void* gsrc) {
    asm volatile("cp.async.ca.shared.global [%0], [%1], 16;" :: "r"(smem_dst), "l"(gsrc));
}

// ---------------- tensor-core GEMM (3-stage cp.async pipeline) --------------
// C[pair, n0..] = A_row(pair) . B[e][n]^T ; 128x128 tile, BK=32, 8 warps(2x4),
// warp tile 64x32, m16n8k8 tf32. A in memory is already tf32-rounded; B (raw
// fp32 weights) is converted post-ldmatrix.
// MODE 0: A = d_xtf (row = pair>>1), C = d_z (stride NF2)     [gemm1]
// MODE 1: A = d_actbuf (row = pair), C = d_y (stride HDIM)    [gemm2]
#define STG_F 9216          // floats per stage: A 128*36 + B 128*36
template<int KDIM, int BROWS, int MODE>
__global__ __launch_bounds__(256)
void mma_gemm_kernel(const float* __restrict__ Bw) {
    extern __shared__ float dynsm[];
    __shared__ int sPair[128];

    const float* A = (MODE == 0) ? d_xtf : d_actbuf;
    float* C       = (MODE == 0) ? d_z   : d_y;
    const int CLD    = (MODE == 0) ? NF2 : HDIM;
    const int ASHIFT = (MODE == 0) ? 1 : 0;

    int e   = blockIdx.z;
    int cnt = d_count[e];
    int m0  = blockIdx.x * 128;
    if (m0 >= cnt) return;
    int n0  = blockIdx.y * 128;

    int tid = threadIdx.x;
    if (tid < 128) {
        int m = m0 + tid;
        sPair[tid] = d_list[e * T_TOK + (m < cnt ? m : cnt - 1)];
    }
    __syncthreads();

    int row  = tid >> 1;          // 0..127
    int hc   = (tid & 1) * 16;    // k-col offset 0/16

    const float* aPtr = A  + (size_t)(sPair[row] >> ASHIFT) * KDIM + hc;
    const float* bPtr = Bw + ((size_t)e * BROWS + n0 + row) * KDIM + hc;
    uint32_t dstOff = (uint32_t)__cvta_generic_to_shared(dynsm) + (row * 36 + hc) * 4u;

    int warp = tid >> 5;
    int lane = tid & 31;
    int wm = warp & 1;
    int wn = warp >> 1;
    int g  = lane >> 2;
    int tg = lane & 3;

    // ldmatrix lane->address mapping (same as verified R5)
    int aSub = lane >> 3;
    int aRowSel = ((aSub & 1) << 3) + (lane & 7);
    int aColSel = (aSub >> 1) << 2;
    int bRowSel = lane & 7;
    int bColSel = ((lane >> 3) & 1) << 2;

    uint32_t sBase = (uint32_t)__cvta_generic_to_shared(dynsm);
    uint32_t aFragOff = ((wm * 64 + aRowSel) * 36 + aColSel) * 4u;
    uint32_t bFragOff = (4608 + (wn * 32 + bRowSel) * 36 + bColSel) * 4u;

    float acc[4][4][4];
#pragma unroll
    for (int i = 0; i < 4; i++)
#pragma unroll
        for (int j = 0; j < 4; j++)
#pragma unroll
            for (int r = 0; r < 4; r++) acc[i][j][r] = 0.f;

    const int NCHUNK = KDIM / 32;

    // prologue: issue chunks 0 and 1
#pragma unroll
    for (int pc = 0; pc < 2; pc++) {
        uint32_t dA = dstOff + (uint32_t)((pc % 3) * STG_F) * 4u;
        const float* sa = aPtr + pc * 32;
        const float* sb = bPtr + pc * 32;
#pragma unroll
        for (int q = 0; q < 4; q++) {
            cp16(dA + q * 16u, sa + q * 4);
            cp16(dA + 4608u * 4u + q * 16u, sb + q * 4);
        }
        asm volatile("cp.async.commit_group;");
    }

    for (int kc = 0; kc < NCHUNK; kc++) {
        asm volatile("cp.async.wait_group 1;");
        __syncthreads();

        int nxt = kc + 2;
        if (nxt < NCHUNK) {
            uint32_t dA = dstOff + (uint32_t)((nxt % 3) * STG_F) * 4u;
            const float* sa = aPtr + nxt * 32;
            const float* sb = bPtr + nxt * 32;
#pragma unroll
            for (int q = 0; q < 4; q++) {
                cp16(dA + q * 16u, sa + q * 4);
                cp16(dA + 4608u * 4u + q * 16u, sb + q * 4);
            }
        }
        asm volatile("cp.async.commit_group;");

        uint32_t stg = sBase + (uint32_t)((kc % 3) * STG_F) * 4u;
        uint32_t aB = stg + aFragOff;
        uint32_t bB = stg + bFragOff;

#pragma unroll
        for (int s = 0; s < 4; s++) {
            uint32_t afr[4][4], bfr[4][2];
#pragma unroll
            for (int i = 0; i < 4; i++)
                ldsm_x4(afr[i], aB + (i * 16 * 36 + s * 8) * 4u);
#pragma unroll
            for (int j = 0; j < 4; j++) {
                ldsm_x2(bfr[j], bB + (j * 8 * 36 + s * 8) * 4u);
                // weights are raw fp32 -> round to tf32 here (8 cvt/lane/s-step)
                bfr[j][0] = f2tf32(__uint_as_float(bfr[j][0]));
                bfr[j][1] = f2tf32(__uint_as_float(bfr[j][1]));
            }
#pragma unroll
            for (int i = 0; i < 4; i++)
#pragma unroll
                for (int j = 0; j < 4; j++)
                    mma_tf32(acc[i][j], afr[i], bfr[j]);
        }
        __syncthreads();
    }

    // epilogue
#pragma unroll
    for (int i = 0; i < 4; i++) {
#pragma unroll
        for (int rr = 0; rr < 2; rr++) {
            int mloc = wm * 64 + i * 16 + rr * 8 + g;
            if (m0 + mloc < cnt) {
                int p = sPair[mloc];
                float* dst = C + (size_t)p * CLD + n0 + wn * 32 + tg * 2;
#pragma unroll
                for (int j = 0; j < 4; j++) {
                    float2 v;
                    v.x = acc[i][j][rr * 2 + 0];
                    v.y = acc[i][j][rr * 2 + 1];
                    *(float2*)(dst + j * 8) = v;
                }
            }
        }
    }
}

// ---------------- act: silu(g)*u, output tf32-rounded ------------------------
__global__ void act_kernel() {
    int i4 = blockIdx.x * blockDim.x + threadIdx.x;       // over NPAIR*FFND/4
    int p  = i4 >> 10;
    int f4 = i4 & 1023;
    if (p >= NPAIR) return;
    const float4* gp = (const float4*)(d_z + (size_t)p * NF2) + f4;
    const float4* up = (const float4*)(d_z + (size_t)p * NF2 + FFND) + f4;
    float4 gv = *gp, uv = *up;
    uint4 r;
    r.x = f2tf32(gv.x / (1.0f + __expf(-gv.x)) * uv.x);
    r.y = f2tf32(gv.y / (1.0f + __expf(-gv.y)) * uv.y);
    r.z = f2tf32(gv.z / (1.0f + __expf(-gv.z)) * uv.z);
    r.w = f2tf32(gv.w / (1.0f + __expf(-gv.w)) * uv.w);
    ((uint4*)(d_actbuf + (size_t)p * FFND))[f4] = r;
}

// ---------------- combine: out[t] = w0*y[2t] + w1*y[2t+1] -------------------
__global__ void combine_kernel(float* __restrict__ out) {
    int i4 = blockIdx.x * blockDim.x + threadIdx.x;
    int t  = i4 >> 8;
    int h4 = i4 & 255;
    if (t >= T_TOK) return;
    float w0 = d_wgt[2 * t], w1 = d_wgt[2 * t + 1];
    const float4* y0 = (const float4*)(d_y + (size_t)(2 * t) * HDIM) + h4;
    const float4* y1 = (const float4*)(d_y + (size_t)(2 * t + 1) * HDIM) + h4;
    float4 a = *y0, b = *y1, r;
    r.x = w0 * a.x + w1 * b.x;
    r.y = w0 * a.y + w1 * b.y;
    r.z = w0 * a.z + w1 * b.z;
    r.w = w0 * a.w + w1 * b.w;
    ((float4*)(out + (size_t)t * HDIM))[h4] = r;
}

// ---------------------------------------------------------------------------
extern "C" void kernel_launch(void* const* d_in, const int* in_sizes, int n_in,
                              void* d_out, int out_size) {
    const float* x   = (const float*)d_in[0];
    const float* gw  = (const float*)d_in[1];
    const float* w13 = (const float*)d_in[2];
    const float* w2  = (const float*)d_in[3];
    float* out = (float*)d_out;
    float* rlogits = out + (size_t)T_TOK * HDIM;

    const int smemBytes = 3 * STG_F * 4;   // 110592
    static int attrDone = 0;
    if (!attrDone) {
        cudaFuncSetAttribute(mma_gemm_kernel<HDIM, NF2, 0>,
                             cudaFuncAttributeMaxDynamicSharedMemorySize, smemBytes);
        cudaFuncSetAttribute(mma_gemm_kernel<FFND, HDIM, 1>,
                             cudaFuncAttributeMaxDynamicSharedMemorySize, smemBytes);
        attrDone = 1;
    }

    zero_counts_kernel<<<1, 32>>>();
    router_kernel<<<T_TOK / 8, 256>>>(x, gw, rlogits);
    convert_x_kernel<<<(T_TOK * HDIM / 4 + 255) / 256, 256>>>(x);

    dim3 g1(T_TOK / 128, NF2 / 128, NE);      // (16, 64, 8)
    mma_gemm_kernel<HDIM, NF2, 0><<<g1, 256, smemBytes>>>(w13);

    act_kernel<<<(NPAIR * FFND / 4) / 256, 256>>>();

    dim3 g2(T_TOK / 128, HDIM / 128, NE);     // (16, 8, 8)
    mma_gemm_kernel<FFND, HDIM, 1><<<g2, 256, smemBytes>>>(w2);

    combine_kernel<<<(T_TOK * HDIM / 4) / 256, 256>>>(out);
}

// round 11
// speedup vs baseline: 1.5802x; 1.5802x over previous
#include <cuda_runtime.h>
#include <cuda_fp16.h>
#include <math.h>
#include <stdint.h>

#define T_TOK 2048
#define HDIM  1024
#define FFND  4096
#define NE    8
#define NF2   8192   // 2*FFND
#define NPAIR (2*T_TOK)

// ---------------- scratch (static device globals; no allocation) ------------
// NOTE: never pass these as kernel args from host (host shadow != device ptr).
__device__ int    d_count[NE];
__device__ int    d_list[NE * T_TOK];
__device__ float  d_wgt[NPAIR];
__device__ float  d_z[(size_t)NPAIR * NF2];       // [pair, 8192] g|u (fp32)
__device__ float  d_actbuf[(size_t)NPAIR * FFND]; // silu(g)*u (fp32)
__device__ float  d_y[(size_t)NPAIR * HDIM];

// ---------------------------------------------------------------------------
__global__ void zero_counts_kernel() {
    if (threadIdx.x < NE) d_count[threadIdx.x] = 0;
}

__device__ __forceinline__ uint32_t pack2h(float lo, float hi) {
    uint32_t r;
    asm("cvt.rn.f16x2.f32 %0, %1, %2;" : "=r"(r) : "f"(hi), "f"(lo));
    return r;
}

__device__ __forceinline__ uint32_t f2tf32(float f) {
    uint32_t r;
    asm("cvt.rna.tf32.f32 %0, %1;" : "=r"(r) : "f"(f));
    return r;
}

// One warp per token: router logits, top-2 softmax weights, expert compaction.
__global__ void router_kernel(const float* __restrict__ x,
                              const float* __restrict__ gw,
                              float* __restrict__ rlogits) {
    int gwarp = (blockIdx.x * blockDim.x + threadIdx.x) >> 5;
    int lane  = threadIdx.x & 31;
    if (gwarp >= T_TOK) return;
    const float* xr = x + (size_t)gwarp * HDIM;

    float acc[NE];
#pragma unroll
    for (int e = 0; e < NE; e++) acc[e] = 0.f;
    for (int h = lane; h < HDIM; h += 32) {
        float xv = xr[h];
#pragma unroll
        for (int e = 0; e < NE; e++) acc[e] += xv * gw[e * HDIM + h];
    }
#pragma unroll
    for (int e = 0; e < NE; e++)
#pragma unroll
        for (int off = 16; off; off >>= 1)
            acc[e] += __shfl_xor_sync(0xffffffffu, acc[e], off);

    if (lane == 0) {
#pragma unroll
        for (int e = 0; e < NE; e++) rlogits[gwarp * NE + e] = acc[e];
        int e0 = 0;
#pragma unroll
        for (int e = 1; e < NE; e++) if (acc[e] > acc[e0]) e0 = e;
        int e1 = (e0 == 0) ? 1 : 0;
#pragma unroll
        for (int e = 0; e < NE; e++)
            if (e != e0 && acc[e] > acc[e1]) e1 = e;
        float p1 = __expf(acc[e1] - acc[e0]);
        float inv = 1.0f / (1.0f + p1);
        d_wgt[gwarp * 2 + 0] = inv;
        d_wgt[gwarp * 2 + 1] = p1 * inv;

        int pos0 = atomicAdd(&d_count[e0], 1);
        d_list[e0 * T_TOK + pos0] = gwarp * 2 + 0;
        int pos1 = atomicAdd(&d_count[e1], 1);
        d_list[e1 * T_TOK + pos1] = gwarp * 2 + 1;
    }
}

// ---------------- mma helpers ------------------------------------------------
__device__ __forceinline__ void mma_f16(float* d, const uint32_t* a, const uint32_t* b) {
    asm volatile(
        "mma.sync.aligned.m16n8k16.row.col.f32.f16.f16.f32 "
        "{%0,%1,%2,%3}, {%4,%5,%6,%7}, {%8,%9}, {%0,%1,%2,%3};\n"
        : "+f"(d[0]), "+f"(d[1]), "+f"(d[2]), "+f"(d[3])
        : "r"(a[0]), "r"(a[1]), "r"(a[2]), "r"(a[3]), "r"(b[0]), "r"(b[1]));
}

__device__ __forceinline__ void mma_tf32(float* d, const uint32_t* a, const uint32_t* b) {
    asm volatile(
        "mma.sync.aligned.m16n8k8.row.col.f32.tf32.tf32.f32 "
        "{%0,%1,%2,%3}, {%4,%5,%6,%7}, {%8,%9}, {%0,%1,%2,%3};\n"
        : "+f"(d[0]), "+f"(d[1]), "+f"(d[2]), "+f"(d[3])
        : "r"(a[0]), "r"(a[1]), "r"(a[2]), "r"(a[3]), "r"(b[0]), "r"(b[1]));
}

__device__ __forceinline__ void ldsm_x4(uint32_t* r, uint32_t addr) {
    asm volatile("ldmatrix.sync.aligned.m8n8.x4.shared.b16 {%0,%1,%2,%3}, [%4];"
                 : "=r"(r[0]), "=r"(r[1]), "=r"(r[2]), "=r"(r[3]) : "r"(addr));
}
__device__ __forceinline__ void ldsm_x2(uint32_t* r, uint32_t addr) {
    asm volatile("ldmatrix.sync.aligned.m8n8.x2.shared.b16 {%0,%1}, [%2];"
                 : "=r"(r[0]), "=r"(r[1]) : "r"(addr));
}

// ---------------- GEMM1: fp16 m16n8k16, direct-LDS fragments ----------------
// z[pair, n0..] = x[token(pair)] . w13[e][n]^T, K=1024. Both A and B are fp32
// in gmem, converted fp32->fp16 at SMEM store. Fragments loaded by plain LDS
// at textbook coordinates (no ldmatrix, no pre-converted inputs).
#define ROWH 40   // SMEM row stride in halves (80 B); conflict-free (row*20+tg mod 32)
__global__ __launch_bounds__(256)
void gemm1_f16_kernel(const float* __restrict__ x, const float* __restrict__ Bw) {
    __shared__ __align__(16) __half As[128][ROWH];
    __shared__ __align__(16) __half Bs[128][ROWH];
    __shared__ int sPair[128];

    int e   = blockIdx.z;
    int cnt = d_count[e];
    int m0  = blockIdx.x * 128;
    if (m0 >= cnt) return;
    int n0  = blockIdx.y * 128;

    int tid = threadIdx.x;
    if (tid < 128) {
        int m = m0 + tid;
        sPair[tid] = d_list[e * T_TOK + (m < cnt ? m : cnt - 1)];
    }
    __syncthreads();

    int row = tid >> 1;           // 0..127
    int hc  = (tid & 1) * 16;     // k offset (fp32 source elems / fp16 dest halves)

    const float* aPtr = x  + (size_t)(sPair[row] >> 1) * HDIM + hc;
    const float* bPtr = Bw + ((size_t)e * NF2 + n0 + row) * HDIM + hc;

    int warp = tid >> 5;
    int lane = tid & 31;
    int wm = warp & 1;            // 64-row slab
    int wn = warp >> 1;           // 32-col slab
    int g  = lane >> 2;           // 0..7
    int tg = lane & 3;            // 0..3

    float acc[4][4][4];
#pragma unroll
    for (int i = 0; i < 4; i++)
#pragma unroll
        for (int j = 0; j < 4; j++)
#pragma unroll
            for (int r = 0; r < 4; r++) acc[i][j][r] = 0.f;

    // prologue fetch (chunk 0): 4 float4 each for A and B
    float4 fa[4], fb[4];
#pragma unroll
    for (int q = 0; q < 4; q++) {
        fa[q] = *(const float4*)(aPtr + q * 4);
        fb[q] = *(const float4*)(bPtr + q * 4);
    }

    const int NCHUNK = HDIM / 32;
    for (int kc = 0; kc < NCHUNK; kc++) {
        // convert + store current chunk (16 halves per side per thread)
        uint4 ua0, ua1, ub0, ub1;
        ua0.x = pack2h(fa[0].x, fa[0].y); ua0.y = pack2h(fa[0].z, fa[0].w);
        ua0.z = pack2h(fa[1].x, fa[1].y); ua0.w = pack2h(fa[1].z, fa[1].w);
        ua1.x = pack2h(fa[2].x, fa[2].y); ua1.y = pack2h(fa[2].z, fa[2].w);
        ua1.z = pack2h(fa[3].x, fa[3].y); ua1.w = pack2h(fa[3].z, fa[3].w);
        ub0.x = pack2h(fb[0].x, fb[0].y); ub0.y = pack2h(fb[0].z, fb[0].w);
        ub0.z = pack2h(fb[1].x, fb[1].y); ub0.w = pack2h(fb[1].z, fb[1].w);
        ub1.x = pack2h(fb[2].x, fb[2].y); ub1.y = pack2h(fb[2].z, fb[2].w);
        ub1.z = pack2h(fb[3].x, fb[3].y); ub1.w = pack2h(fb[3].z, fb[3].w);
        *(uint4*)&As[row][hc + 0] = ua0;
        *(uint4*)&As[row][hc + 8] = ua1;
        *(uint4*)&Bs[row][hc + 0] = ub0;
        *(uint4*)&Bs[row][hc + 8] = ub1;
        __syncthreads();

        // prefetch next chunk
        if (kc + 1 < NCHUNK) {
            const float* ap = aPtr + (kc + 1) * 32;
            const float* bp = bPtr + (kc + 1) * 32;
#pragma unroll
            for (int q = 0; q < 4; q++) {
                fa[q] = *(const float4*)(ap + q * 4);
                fb[q] = *(const float4*)(bp + q * 4);
            }
        }

#pragma unroll
        for (int s = 0; s < 2; s++) {         // two k16 steps per 32-chunk
            int k0 = s * 16;
            uint32_t afr[4][4], bfr[4][2];
#pragma unroll
            for (int i = 0; i < 4; i++) {
                int R = wm * 64 + i * 16;
                afr[i][0] = *(const uint32_t*)&As[R + g    ][k0 + 2 * tg    ];
                afr[i][1] = *(const uint32_t*)&As[R + g + 8][k0 + 2 * tg    ];
                afr[i][2] = *(const uint32_t*)&As[R + g    ][k0 + 2 * tg + 8];
                afr[i][3] = *(const uint32_t*)&As[R + g + 8][k0 + 2 * tg + 8];
            }
#pragma unroll
            for (int j = 0; j < 4; j++) {
                int N = wn * 32 + j * 8;
                bfr[j][0] = *(const uint32_t*)&Bs[N + g][k0 + 2 * tg    ];
                bfr[j][1] = *(const uint32_t*)&Bs[N + g][k0 + 2 * tg + 8];
            }
#pragma unroll
            for (int i = 0; i < 4; i++)
#pragma unroll
                for (int j = 0; j < 4; j++)
                    mma_f16(acc[i][j], afr[i], bfr[j]);
        }
        __syncthreads();
    }

    // epilogue: D rows g, g+8 of each 16-row atom; cols 2tg, 2tg+1 per 8-col atom
#pragma unroll
    for (int i = 0; i < 4; i++) {
#pragma unroll
        for (int rr = 0; rr < 2; rr++) {
            int mloc = wm * 64 + i * 16 + rr * 8 + g;
            if (m0 + mloc < cnt) {
                int p = sPair[mloc];
                float* dst = d_z + (size_t)p * NF2 + n0 + wn * 32 + tg * 2;
#pragma unroll
                for (int j = 0; j < 4; j++) {
                    float2 v;
                    v.x = acc[i][j][rr * 2 + 0];
                    v.y = acc[i][j][rr * 2 + 1];
                    *(float2*)(dst + j * 8) = v;
                }
            }
        }
    }
}

// ---------------- GEMM2: R5 tf32 kernel (verbatim, known-good) --------------
// y[pair, n0..] = actbuf[pair] . w2[e][n]^T, K=4096.
__global__ __launch_bounds__(256)
void gemm2_tf32_kernel(const float* __restrict__ Bw) {
    const int KDIM = FFND;

    __shared__ float As[128][36];
    __shared__ float Bs[128][36];
    __shared__ int   sPair[128];

    int e   = blockIdx.z;
    int cnt = d_count[e];
    int m0  = blockIdx.x * 128;
    if (m0 >= cnt) return;
    int n0  = blockIdx.y * 128;

    int tid = threadIdx.x;
    if (tid < 128) {
        int m = m0 + tid;
        sPair[tid] = d_list[e * T_TOK + (m < cnt ? m : cnt - 1)];
    }
    __syncthreads();

    int row  = tid >> 1;
    int hc   = (tid & 1) * 16;

    const float* aPtr = d_actbuf + (size_t)sPair[row] * KDIM + hc;
    const float* bPtr = Bw + ((size_t)e * HDIM + n0 + row) * KDIM + hc;

    int warp = tid >> 5;
    int lane = tid & 31;
    int wm = warp & 1;
    int wn = warp >> 1;
    int g  = lane >> 2;
    int tg = lane & 3;

    int aSub = lane >> 3;
    int aRowSel = ((aSub & 1) << 3) + (lane & 7);
    int aColSel = (aSub >> 1) << 2;
    int bRowSel = lane & 7;
    int bColSel = ((lane >> 3) & 1) << 2;

    uint32_t sAs = (uint32_t)__cvta_generic_to_shared(&As[0][0]);
    uint32_t sBs = (uint32_t)__cvta_generic_to_shared(&Bs[0][0]);
    uint32_t aBase = sAs + ((wm * 64 + aRowSel) * 36 + aColSel) * 4u;
    uint32_t bBase = sBs + ((wn * 32 + bRowSel) * 36 + bColSel) * 4u;

    float acc[4][4][4];
#pragma unroll
    for (int i = 0; i < 4; i++)
#pragma unroll
        for (int j = 0; j < 4; j++)
#pragma unroll
            for (int r = 0; r < 4; r++) acc[i][j][r] = 0.f;

    float4 fa[4], fb[4];
#pragma unroll
    for (int q = 0; q < 4; q++) {
        fa[q] = *(const float4*)(aPtr + q * 4);
        fb[q] = *(const float4*)(bPtr + q * 4);
    }

    const int NCHUNK = KDIM / 32;
    for (int kc = 0; kc < NCHUNK; kc++) {
#pragma unroll
        for (int q = 0; q < 4; q++) {
            uint4 ua, ub;
            ua.x = f2tf32(fa[q].x); ua.y = f2tf32(fa[q].y);
            ua.z = f2tf32(fa[q].z); ua.w = f2tf32(fa[q].w);
            ub.x = f2tf32(fb[q].x); ub.y = f2tf32(fb[q].y);
            ub.z = f2tf32(fb[q].z); ub.w = f2tf32(fb[q].w);
            *(uint4*)&As[row][hc + q * 4] = ua;
            *(uint4*)&Bs[row][hc + q * 4] = ub;
        }
        __syncthreads();

        if (kc + 1 < NCHUNK) {
            const float* ap = aPtr + (kc + 1) * 32;
            const float* bp = bPtr + (kc + 1) * 32;
#pragma unroll
            for (int q = 0; q < 4; q++) {
                fa[q] = *(const float4*)(ap + q * 4);
                fb[q] = *(const float4*)(bp + q * 4);
            }
        }

#pragma unroll
        for (int s = 0; s < 4; s++) {
            uint32_t afr[4][4], bfr[4][2];
#pragma unroll
            for (int i = 0; i < 4; i++)
                ldsm_x4(afr[i], aBase + (i * 16 * 36 + s * 8) * 4u);
#pragma unroll
            for (int j = 0; j < 4; j++)
                ldsm_x2(bfr[j], bBase + (j * 8 * 36 + s * 8) * 4u);
#pragma unroll
            for (int i = 0; i < 4; i++)
#pragma unroll
                for (int j = 0; j < 4; j++)
                    mma_tf32(acc[i][j], afr[i], bfr[j]);
        }
        __syncthreads();
    }

#pragma unroll
    for (int i = 0; i < 4; i++) {
#pragma unroll
        for (int rr = 0; rr < 2; rr++) {
            int mloc = wm * 64 + i * 16 + rr * 8 + g;
            if (m0 + mloc < cnt) {
                int p = sPair[mloc];
                float* dst = d_y + (size_t)p * HDIM + n0 + wn * 32 + tg * 2;
#pragma unroll
                for (int j = 0; j < 4; j++) {
                    float2 v;
                    v.x = acc[i][j][rr * 2 + 0];
                    v.y = acc[i][j][rr * 2 + 1];
                    *(float2*)(dst + j * 8) = v;
                }
            }
        }
    }
}

// ---------------- act: silu(g) * u  (float4, fp32 out) ----------------------
__global__ void act_kernel() {
    int i4 = blockIdx.x * blockDim.x + threadIdx.x;       // over NPAIR*FFND/4
    int p  = i4 >> 10;
    int f4 = i4 & 1023;
    if (p >= NPAIR) return;
    const float4* gp = (const float4*)(d_z + (size_t)p * NF2) + f4;
    const float4* up = (const float4*)(d_z + (size_t)p * NF2 + FFND) + f4;
    float4 gv = *gp, uv = *up, r;
    r.x = gv.x / (1.0f + __expf(-gv.x)) * uv.x;
    r.y = gv.y / (1.0f + __expf(-gv.y)) * uv.y;
    r.z = gv.z / (1.0f + __expf(-gv.z)) * uv.z;
    r.w = gv.w / (1.0f + __expf(-gv.w)) * uv.w;
    ((float4*)(d_actbuf + (size_t)p * FFND))[f4] = r;
}

// ---------------- combine: out[t] = w0*y[2t] + w1*y[2t+1] -------------------
__global__ void combine_kernel(float* __restrict__ out) {
    int i4 = blockIdx.x * blockDim.x + threadIdx.x;
    int t  = i4 >> 8;
    int h4 = i4 & 255;
    if (t >= T_TOK) return;
    float w0 = d_wgt[2 * t], w1 = d_wgt[2 * t + 1];
    const float4* y0 = (const float4*)(d_y + (size_t)(2 * t) * HDIM) + h4;
    const float4* y1 = (const float4*)(d_y + (size_t)(2 * t + 1) * HDIM) + h4;
    float4 a = *y0, b = *y1, r;
    r.x = w0 * a.x + w1 * b.x;
    r.y = w0 * a.y + w1 * b.y;
    r.z = w0 * a.z + w1 * b.z;
    r.w = w0 * a.w + w1 * b.w;
    ((float4*)(out + (size_t)t * HDIM))[h4] = r;
}

// ---------------------------------------------------------------------------
extern "C" void kernel_launch(void* const* d_in, const int* in_sizes, int n_in,
                              void* d_out, int out_size) {
    const float* x   = (const float*)d_in[0];
    const float* gw  = (const float*)d_in[1];
    const float* w13 = (const float*)d_in[2];
    const float* w2  = (const float*)d_in[3];
    float* out = (float*)d_out;
    float* rlogits = out + (size_t)T_TOK * HDIM;

    zero_counts_kernel<<<1, 32>>>();
    router_kernel<<<T_TOK / 8, 256>>>(x, gw, rlogits);

    // GEMM1 (fp16 mma, direct-LDS fragments): z = x . w13[e]^T, K=1024
    dim3 g1(T_TOK / 128, NF2 / 128, NE);      // (16, 64, 8)
    gemm1_f16_kernel<<<g1, 256>>>(x, w13);

    act_kernel<<<(NPAIR * FFND / 4) / 256, 256>>>();

    // GEMM2 (tf32 mma, known-good): y = act . w2[e]^T, K=4096
    dim3 g2(T_TOK / 128, HDIM / 128, NE);     // (16, 8, 8)
    gemm2_tf32_kernel<<<g2, 256>>>(w2);

    combine_kernel<<<(T_TOK * HDIM / 4) / 256, 256>>>(out);
}

// round 12
// speedup vs baseline: 1.7342x; 1.0975x over previous
#include <cuda_runtime.h>
#include <cuda_fp16.h>
#include <math.h>
#include <stdint.h>

#define T_TOK 2048
#define HDIM  1024
#define FFND  4096
#define NE    8
#define NF2   8192   // 2*FFND
#define NPAIR (2*T_TOK)

// ---------------- scratch (static device globals; no allocation) ------------
// NOTE: never pass these as kernel args from host (host shadow != device ptr).
__device__ int    d_count[NE];
__device__ int    d_list[NE * T_TOK];
__device__ float  d_wgt[NPAIR];
__device__ __half d_zh[(size_t)NPAIR * NF2];      // [pair, 8192] g|u (fp16)
__device__ __half d_acth[(size_t)NPAIR * FFND];   // silu(g)*u (fp16)
__device__ float  d_y[(size_t)NPAIR * HDIM];

// ---------------------------------------------------------------------------
__global__ void zero_counts_kernel() {
    if (threadIdx.x < NE) d_count[threadIdx.x] = 0;
}

__device__ __forceinline__ uint32_t pack2h(float lo, float hi) {
    uint32_t r;
    asm("cvt.rn.f16x2.f32 %0, %1, %2;" : "=r"(r) : "f"(hi), "f"(lo));
    return r;
}

// One warp per token: router logits, top-2 softmax weights, expert compaction.
__global__ void router_kernel(const float* __restrict__ x,
                              const float* __restrict__ gw,
                              float* __restrict__ rlogits) {
    int gwarp = (blockIdx.x * blockDim.x + threadIdx.x) >> 5;
    int lane  = threadIdx.x & 31;
    if (gwarp >= T_TOK) return;
    const float* xr = x + (size_t)gwarp * HDIM;

    float acc[NE];
#pragma unroll
    for (int e = 0; e < NE; e++) acc[e] = 0.f;
    for (int h = lane; h < HDIM; h += 32) {
        float xv = xr[h];
#pragma unroll
        for (int e = 0; e < NE; e++) acc[e] += xv * gw[e * HDIM + h];
    }
#pragma unroll
    for (int e = 0; e < NE; e++)
#pragma unroll
        for (int off = 16; off; off >>= 1)
            acc[e] += __shfl_xor_sync(0xffffffffu, acc[e], off);

    if (lane == 0) {
#pragma unroll
        for (int e = 0; e < NE; e++) rlogits[gwarp * NE + e] = acc[e];
        int e0 = 0;
#pragma unroll
        for (int e = 1; e < NE; e++) if (acc[e] > acc[e0]) e0 = e;
        int e1 = (e0 == 0) ? 1 : 0;
#pragma unroll
        for (int e = 0; e < NE; e++)
            if (e != e0 && acc[e] > acc[e1]) e1 = e;
        float p1 = __expf(acc[e1] - acc[e0]);
        float inv = 1.0f / (1.0f + p1);
        d_wgt[gwarp * 2 + 0] = inv;
        d_wgt[gwarp * 2 + 1] = p1 * inv;

        int pos0 = atomicAdd(&d_count[e0], 1);
        d_list[e0 * T_TOK + pos0] = gwarp * 2 + 0;
        int pos1 = atomicAdd(&d_count[e1], 1);
        d_list[e1 * T_TOK + pos1] = gwarp * 2 + 1;
    }
}

// ---------------- mma helper -------------------------------------------------
__device__ __forceinline__ void mma_f16(float* d, const uint32_t* a, const uint32_t* b) {
    asm volatile(
        "mma.sync.aligned.m16n8k16.row.col.f32.f16.f16.f32 "
        "{%0,%1,%2,%3}, {%4,%5,%6,%7}, {%8,%9}, {%0,%1,%2,%3};\n"
        : "+f"(d[0]), "+f"(d[1]), "+f"(d[2]), "+f"(d[3])
        : "r"(a[0]), "r"(a[1]), "r"(a[2]), "r"(a[3]), "r"(b[0]), "r"(b[1]));
}

// ---------------- GEMM1: fp16 m16n8k16, direct-LDS fragments ----------------
// z[pair, n0..] = x[token(pair)] . w13[e][n]^T, K=1024. A,B fp32 in gmem,
// converted fp32->fp16 at SMEM store. Output z stored as fp16.
#define ROWH 40   // SMEM row stride in halves (80 B); conflict-free
__global__ __launch_bounds__(256)
void gemm1_f16_kernel(const float* __restrict__ x, const float* __restrict__ Bw) {
    __shared__ __align__(16) __half As[128][ROWH];
    __shared__ __align__(16) __half Bs[128][ROWH];
    __shared__ int sPair[128];

    int e   = blockIdx.z;
    int cnt = d_count[e];
    int m0  = blockIdx.x * 128;
    if (m0 >= cnt) return;
    int n0  = blockIdx.y * 128;

    int tid = threadIdx.x;
    if (tid < 128) {
        int m = m0 + tid;
        sPair[tid] = d_list[e * T_TOK + (m < cnt ? m : cnt - 1)];
    }
    __syncthreads();

    int row = tid >> 1;           // 0..127
    int hc  = (tid & 1) * 16;     // k offset

    const float* aPtr = x  + (size_t)(sPair[row] >> 1) * HDIM + hc;
    const float* bPtr = Bw + ((size_t)e * NF2 + n0 + row) * HDIM + hc;

    int warp = tid >> 5;
    int lane = tid & 31;
    int wm = warp & 1;
    int wn = warp >> 1;
    int g  = lane >> 2;
    int tg = lane & 3;

    float acc[4][4][4];
#pragma unroll
    for (int i = 0; i < 4; i++)
#pragma unroll
        for (int j = 0; j < 4; j++)
#pragma unroll
            for (int r = 0; r < 4; r++) acc[i][j][r] = 0.f;

    float4 fa[4], fb[4];
#pragma unroll
    for (int q = 0; q < 4; q++) {
        fa[q] = *(const float4*)(aPtr + q * 4);
        fb[q] = *(const float4*)(bPtr + q * 4);
    }

    const int NCHUNK = HDIM / 32;
    for (int kc = 0; kc < NCHUNK; kc++) {
        uint4 ua0, ua1, ub0, ub1;
        ua0.x = pack2h(fa[0].x, fa[0].y); ua0.y = pack2h(fa[0].z, fa[0].w);
        ua0.z = pack2h(fa[1].x, fa[1].y); ua0.w = pack2h(fa[1].z, fa[1].w);
        ua1.x = pack2h(fa[2].x, fa[2].y); ua1.y = pack2h(fa[2].z, fa[2].w);
        ua1.z = pack2h(fa[3].x, fa[3].y); ua1.w = pack2h(fa[3].z, fa[3].w);
        ub0.x = pack2h(fb[0].x, fb[0].y); ub0.y = pack2h(fb[0].z, fb[0].w);
        ub0.z = pack2h(fb[1].x, fb[1].y); ub0.w = pack2h(fb[1].z, fb[1].w);
        ub1.x = pack2h(fb[2].x, fb[2].y); ub1.y = pack2h(fb[2].z, fb[2].w);
        ub1.z = pack2h(fb[3].x, fb[3].y); ub1.w = pack2h(fb[3].z, fb[3].w);
        *(uint4*)&As[row][hc + 0] = ua0;
        *(uint4*)&As[row][hc + 8] = ua1;
        *(uint4*)&Bs[row][hc + 0] = ub0;
        *(uint4*)&Bs[row][hc + 8] = ub1;
        __syncthreads();

        if (kc + 1 < NCHUNK) {
            const float* ap = aPtr + (kc + 1) * 32;
            const float* bp = bPtr + (kc + 1) * 32;
#pragma unroll
            for (int q = 0; q < 4; q++) {
                fa[q] = *(const float4*)(ap + q * 4);
                fb[q] = *(const float4*)(bp + q * 4);
            }
        }

#pragma unroll
        for (int s = 0; s < 2; s++) {
            int k0 = s * 16;
            uint32_t afr[4][4], bfr[4][2];
#pragma unroll
            for (int i = 0; i < 4; i++) {
                int R = wm * 64 + i * 16;
                afr[i][0] = *(const uint32_t*)&As[R + g    ][k0 + 2 * tg    ];
                afr[i][1] = *(const uint32_t*)&As[R + g + 8][k0 + 2 * tg    ];
                afr[i][2] = *(const uint32_t*)&As[R + g    ][k0 + 2 * tg + 8];
                afr[i][3] = *(const uint32_t*)&As[R + g + 8][k0 + 2 * tg + 8];
            }
#pragma unroll
            for (int j = 0; j < 4; j++) {
                int N = wn * 32 + j * 8;
                bfr[j][0] = *(const uint32_t*)&Bs[N + g][k0 + 2 * tg    ];
                bfr[j][1] = *(const uint32_t*)&Bs[N + g][k0 + 2 * tg + 8];
            }
#pragma unroll
            for (int i = 0; i < 4; i++)
#pragma unroll
                for (int j = 0; j < 4; j++)
                    mma_f16(acc[i][j], afr[i], bfr[j]);
        }
        __syncthreads();
    }

    // epilogue: pack fp32 acc pairs -> fp16, store 4B per j-tile
#pragma unroll
    for (int i = 0; i < 4; i++) {
#pragma unroll
        for (int rr = 0; rr < 2; rr++) {
            int mloc = wm * 64 + i * 16 + rr * 8 + g;
            if (m0 + mloc < cnt) {
                int p = sPair[mloc];
                __half* dst = d_zh + (size_t)p * NF2 + n0 + wn * 32 + tg * 2;
#pragma unroll
                for (int j = 0; j < 4; j++)
                    *(uint32_t*)(dst + j * 8) =
                        pack2h(acc[i][j][rr * 2 + 0], acc[i][j][rr * 2 + 1]);
            }
        }
    }
}

// ---------------- GEMM2: fp16 m16n8k16, direct-LDS fragments ----------------
// y[pair, n0..] = acth[pair] . w2[e][n]^T, K=4096. A already fp16 in gmem
// (no cvt); B fp32 -> fp16 at SMEM store. Output y fp32.
__global__ __launch_bounds__(256)
void gemm2_f16_kernel(const float* __restrict__ Bw) {
    __shared__ __align__(16) __half As[128][ROWH];
    __shared__ __align__(16) __half Bs[128][ROWH];
    __shared__ int sPair[128];

    int e   = blockIdx.z;
    int cnt = d_count[e];
    int m0  = blockIdx.x * 128;
    if (m0 >= cnt) return;
    int n0  = blockIdx.y * 128;

    int tid = threadIdx.x;
    if (tid < 128) {
        int m = m0 + tid;
        sPair[tid] = d_list[e * T_TOK + (m < cnt ? m : cnt - 1)];
    }
    __syncthreads();

    int row = tid >> 1;
    int hc  = (tid & 1) * 16;

    const __half* aPtr = d_acth + (size_t)sPair[row] * FFND + hc;
    const float*  bPtr = Bw + ((size_t)e * HDIM + n0 + row) * FFND + hc;

    int warp = tid >> 5;
    int lane = tid & 31;
    int wm = warp & 1;
    int wn = warp >> 1;
    int g  = lane >> 2;
    int tg = lane & 3;

    float acc[4][4][4];
#pragma unroll
    for (int i = 0; i < 4; i++)
#pragma unroll
        for (int j = 0; j < 4; j++)
#pragma unroll
            for (int r = 0; r < 4; r++) acc[i][j][r] = 0.f;

    // A: 16 halves = 2 x uint4 ; B: 16 floats = 4 x float4
    uint4  fa[2];
    float4 fb[4];
    fa[0] = *(const uint4*)(aPtr);
    fa[1] = *(const uint4*)(aPtr + 8);
#pragma unroll
    for (int q = 0; q < 4; q++) fb[q] = *(const float4*)(bPtr + q * 4);

    const int NCHUNK = FFND / 32;
    for (int kc = 0; kc < NCHUNK; kc++) {
        uint4 ub0, ub1;
        ub0.x = pack2h(fb[0].x, fb[0].y); ub0.y = pack2h(fb[0].z, fb[0].w);
        ub0.z = pack2h(fb[1].x, fb[1].y); ub0.w = pack2h(fb[1].z, fb[1].w);
        ub1.x = pack2h(fb[2].x, fb[2].y); ub1.y = pack2h(fb[2].z, fb[2].w);
        ub1.z = pack2h(fb[3].x, fb[3].y); ub1.w = pack2h(fb[3].z, fb[3].w);
        *(uint4*)&As[row][hc + 0] = fa[0];
        *(uint4*)&As[row][hc + 8] = fa[1];
        *(uint4*)&Bs[row][hc + 0] = ub0;
        *(uint4*)&Bs[row][hc + 8] = ub1;
        __syncthreads();

        if (kc + 1 < NCHUNK) {
            const __half* ap = aPtr + (kc + 1) * 32;
            const float*  bp = bPtr + (kc + 1) * 32;
            fa[0] = *(const uint4*)(ap);
            fa[1] = *(const uint4*)(ap + 8);
#pragma unroll
            for (int q = 0; q < 4; q++) fb[q] = *(const float4*)(bp + q * 4);
        }

#pragma unroll
        for (int s = 0; s < 2; s++) {
            int k0 = s * 16;
            uint32_t afr[4][4], bfr[4][2];
#pragma unroll
            for (int i = 0; i < 4; i++) {
                int R = wm * 64 + i * 16;
                afr[i][0] = *(const uint32_t*)&As[R + g    ][k0 + 2 * tg    ];
                afr[i][1] = *(const uint32_t*)&As[R + g + 8][k0 + 2 * tg    ];
                afr[i][2] = *(const uint32_t*)&As[R + g    ][k0 + 2 * tg + 8];
                afr[i][3] = *(const uint32_t*)&As[R + g + 8][k0 + 2 * tg + 8];
            }
#pragma unroll
            for (int j = 0; j < 4; j++) {
                int N = wn * 32 + j * 8;
                bfr[j][0] = *(const uint32_t*)&Bs[N + g][k0 + 2 * tg    ];
                bfr[j][1] = *(const uint32_t*)&Bs[N + g][k0 + 2 * tg + 8];
            }
#pragma unroll
            for (int i = 0; i < 4; i++)
#pragma unroll
                for (int j = 0; j < 4; j++)
                    mma_f16(acc[i][j], afr[i], bfr[j]);
        }
        __syncthreads();
    }

#pragma unroll
    for (int i = 0; i < 4; i++) {
#pragma unroll
        for (int rr = 0; rr < 2; rr++) {
            int mloc = wm * 64 + i * 16 + rr * 8 + g;
            if (m0 + mloc < cnt) {
                int p = sPair[mloc];
                float* dst = d_y + (size_t)p * HDIM + n0 + wn * 32 + tg * 2;
#pragma unroll
                for (int j = 0; j < 4; j++) {
                    float2 v;
                    v.x = acc[i][j][rr * 2 + 0];
                    v.y = acc[i][j][rr * 2 + 1];
                    *(float2*)(dst + j * 8) = v;
                }
            }
        }
    }
}

// ---------------- act: silu(g)*u, half in / half out -------------------------
__global__ void act_kernel() {
    int i8 = blockIdx.x * blockDim.x + threadIdx.x;   // over NPAIR*FFND/8
    int p  = i8 >> 9;                                 // / (FFND/8)
    int f8 = i8 & 511;
    if (p >= NPAIR) return;
    const uint4* gp = (const uint4*)(d_zh + (size_t)p * NF2) + f8;
    const uint4* up = (const uint4*)(d_zh + (size_t)p * NF2 + FFND) + f8;
    uint4 gu = *gp, uu = *up, o;
    const __half2* gh = (const __half2*)&gu;
    const __half2* uh = (const __half2*)&uu;
    uint32_t* oh = (uint32_t*)&o;
#pragma unroll
    for (int q = 0; q < 4; q++) {
        float2 gf = __half22float2(gh[q]);
        float2 uf = __half22float2(uh[q]);
        float r0 = gf.x / (1.0f + __expf(-gf.x)) * uf.x;
        float r1 = gf.y / (1.0f + __expf(-gf.y)) * uf.y;
        oh[q] = pack2h(r0, r1);
    }
    ((uint4*)(d_acth + (size_t)p * FFND))[f8] = o;
}

// ---------------- combine: out[t] = w0*y[2t] + w1*y[2t+1] -------------------
__global__ void combine_kernel(float* __restrict__ out) {
    int i4 = blockIdx.x * blockDim.x + threadIdx.x;
    int t  = i4 >> 8;
    int h4 = i4 & 255;
    if (t >= T_TOK) return;
    float w0 = d_wgt[2 * t], w1 = d_wgt[2 * t + 1];
    const float4* y0 = (const float4*)(d_y + (size_t)(2 * t) * HDIM) + h4;
    const float4* y1 = (const float4*)(d_y + (size_t)(2 * t + 1) * HDIM) + h4;
    float4 a = *y0, b = *y1, r;
    r.x = w0 * a.x + w1 * b.x;
    r.y = w0 * a.y + w1 * b.y;
    r.z = w0 * a.z + w1 * b.z;
    r.w = w0 * a.w + w1 * b.w;
    ((float4*)(out + (size_t)t * HDIM))[h4] = r;
}

// ---------------------------------------------------------------------------
extern "C" void kernel_launch(void* const* d_in, const int* in_sizes, int n_in,
                              void* d_out, int out_size) {
    const float* x   = (const float*)d_in[0];
    const float* gw  = (const float*)d_in[1];
    const float* w13 = (const float*)d_in[2];
    const float* w2  = (const float*)d_in[3];
    float* out = (float*)d_out;
    float* rlogits = out + (size_t)T_TOK * HDIM;

    zero_counts_kernel<<<1, 32>>>();
    router_kernel<<<T_TOK / 8, 256>>>(x, gw, rlogits);

    // GEMM1 (fp16 mma): z_h = x . w13[e]^T, K=1024
    dim3 g1(T_TOK / 128, NF2 / 128, NE);      // (16, 64, 8)
    gemm1_f16_kernel<<<g1, 256>>>(x, w13);

    act_kernel<<<(NPAIR * FFND / 8) / 256, 256>>>();

    // GEMM2 (fp16 mma): y = act_h . w2[e]^T, K=4096
    dim3 g2(T_TOK / 128, HDIM / 128, NE);     // (16, 8, 8)
    gemm2_f16_kernel<<<g2, 256>>>(w2);

    combine_kernel<<<(T_TOK * HDIM / 4) / 256, 256>>>(out);
}

// round 13
// speedup vs baseline: 1.9457x; 1.1219x over previous
#include <cuda_runtime.h>
#include <cuda_fp16.h>
#include <math.h>
#include <stdint.h>

#define T_TOK 2048
#define HDIM  1024
#define FFND  4096
#define NE    8
#define NF2   8192   // 2*FFND
#define NPAIR (2*T_TOK)

// ---------------- scratch (static device globals; no allocation) ------------
// NOTE: never pass these as kernel args from host (host shadow != device ptr).
__device__ int    d_count[NE];
__device__ int    d_list[NE * T_TOK];
__device__ float  d_wgt[NPAIR];
__device__ __half d_xh[(size_t)T_TOK * HDIM];         // x fp16
__device__ __half d_w13h[(size_t)NE * NF2 * HDIM];    // w13 fp16 (128 MB)
__device__ __half d_w2h[(size_t)NE * HDIM * FFND];    // w2 fp16 (64 MB)
__device__ __half d_zh[(size_t)NPAIR * NF2];          // g|u fp16
__device__ __half d_acth[(size_t)NPAIR * FFND];       // silu(g)*u fp16
__device__ float  d_y[(size_t)NPAIR * HDIM];

// ---------------------------------------------------------------------------
__global__ void zero_counts_kernel() {
    if (threadIdx.x < NE) d_count[threadIdx.x] = 0;
}

__device__ __forceinline__ uint32_t pack2h(float lo, float hi) {
    uint32_t r;
    asm("cvt.rn.f16x2.f32 %0, %1, %2;" : "=r"(r) : "f"(hi), "f"(lo));
    return r;
}

// One warp per token: router logits, top-2 softmax weights, expert compaction.
__global__ void router_kernel(const float* __restrict__ x,
                              const float* __restrict__ gw,
                              float* __restrict__ rlogits) {
    int gwarp = (blockIdx.x * blockDim.x + threadIdx.x) >> 5;
    int lane  = threadIdx.x & 31;
    if (gwarp >= T_TOK) return;
    const float* xr = x + (size_t)gwarp * HDIM;

    float acc[NE];
#pragma unroll
    for (int e = 0; e < NE; e++) acc[e] = 0.f;
    for (int h = lane; h < HDIM; h += 32) {
        float xv = xr[h];
#pragma unroll
        for (int e = 0; e < NE; e++) acc[e] += xv * gw[e * HDIM + h];
    }
#pragma unroll
    for (int e = 0; e < NE; e++)
#pragma unroll
        for (int off = 16; off; off >>= 1)
            acc[e] += __shfl_xor_sync(0xffffffffu, acc[e], off);

    if (lane == 0) {
#pragma unroll
        for (int e = 0; e < NE; e++) rlogits[gwarp * NE + e] = acc[e];
        int e0 = 0;
#pragma unroll
        for (int e = 1; e < NE; e++) if (acc[e] > acc[e0]) e0 = e;
        int e1 = (e0 == 0) ? 1 : 0;
#pragma unroll
        for (int e = 0; e < NE; e++)
            if (e != e0 && acc[e] > acc[e1]) e1 = e;
        float p1 = __expf(acc[e1] - acc[e0]);
        float inv = 1.0f / (1.0f + p1);
        d_wgt[gwarp * 2 + 0] = inv;
        d_wgt[gwarp * 2 + 1] = p1 * inv;

        int pos0 = atomicAdd(&d_count[e0], 1);
        d_list[e0 * T_TOK + pos0] = gwarp * 2 + 0;
        int pos1 = atomicAdd(&d_count[e1], 1);
        d_list[e1 * T_TOK + pos1] = gwarp * 2 + 1;
    }
}

// Convert x to fp16.
__global__ void convert_x_kernel(const float* __restrict__ x) {
    int i8 = blockIdx.x * blockDim.x + threadIdx.x;   // over T*H/8
    if (i8 >= T_TOK * HDIM / 8) return;
    float4 v0 = ((const float4*)x)[i8 * 2 + 0];
    float4 v1 = ((const float4*)x)[i8 * 2 + 1];
    uint4 u;
    u.x = pack2h(v0.x, v0.y);
    u.y = pack2h(v0.z, v0.w);
    u.z = pack2h(v1.x, v1.y);
    u.w = pack2h(v1.z, v1.w);
    ((uint4*)d_xh)[i8] = u;
}

// Convert w13 + w2 to fp16 (8 floats / thread, single grid).
__global__ void convert_w_kernel(const float* __restrict__ w13,
                                 const float* __restrict__ w2) {
    size_t i8 = (size_t)blockIdx.x * blockDim.x + threadIdx.x;
    const size_t n13 = (size_t)NE * NF2 * HDIM / 8;   // 8388608
    const size_t n2  = (size_t)NE * HDIM * FFND / 8;  // 4194304
    if (i8 < n13) {
        float4 v0 = ((const float4*)w13)[i8 * 2 + 0];
        float4 v1 = ((const float4*)w13)[i8 * 2 + 1];
        uint4 u;
        u.x = pack2h(v0.x, v0.y); u.y = pack2h(v0.z, v0.w);
        u.z = pack2h(v1.x, v1.y); u.w = pack2h(v1.z, v1.w);
        ((uint4*)d_w13h)[i8] = u;
    } else if (i8 < n13 + n2) {
        size_t j = i8 - n13;
        float4 v0 = ((const float4*)w2)[j * 2 + 0];
        float4 v1 = ((const float4*)w2)[j * 2 + 1];
        uint4 u;
        u.x = pack2h(v0.x, v0.y); u.y = pack2h(v0.z, v0.w);
        u.z = pack2h(v1.x, v1.y); u.w = pack2h(v1.z, v1.w);
        ((uint4*)d_w2h)[j] = u;
    }
}

// ---------------- mma helper -------------------------------------------------
__device__ __forceinline__ void mma_f16(float* d, const uint32_t* a, const uint32_t* b) {
    asm volatile(
        "mma.sync.aligned.m16n8k16.row.col.f32.f16.f16.f32 "
        "{%0,%1,%2,%3}, {%4,%5,%6,%7}, {%8,%9}, {%0,%1,%2,%3};\n"
        : "+f"(d[0]), "+f"(d[1]), "+f"(d[2]), "+f"(d[3])
        : "r"(a[0]), "r"(a[1]), "r"(a[2]), "r"(a[3]), "r"(b[0]), "r"(b[1]));
}

// ---------------- fp16 GEMM, direct-LDS fragments, double-buffered ----------
// C[pair, n0..] = A_row(pair) . B[e][n]^T ; 128x128 tile, BK=32, 8 warps(2x4),
// warp tile 64x32, m16n8k16. A and B both fp16 in gmem (no cvt in loop).
// MODE 0: A = d_xh (row = pair>>1), B = d_w13h, C = d_zh fp16 (stride NF2)
// MODE 1: A = d_acth (row = pair),  B = d_w2h,  C = d_y fp32 (stride HDIM)
#define ROWH 40   // SMEM row stride in halves (80 B); conflict-free
template<int KDIM, int BROWS, int MODE>
__global__ __launch_bounds__(256)
void gemm_f16_kernel() {
    const __half* A  = (MODE == 0) ? d_xh   : d_acth;
    const __half* Bw = (MODE == 0) ? d_w13h : d_w2h;
    const int ASHIFT = (MODE == 0) ? 1 : 0;

    __shared__ __align__(16) __half As[2][128][ROWH];
    __shared__ __align__(16) __half Bs[2][128][ROWH];
    __shared__ int sPair[128];

    int e   = blockIdx.z;
    int cnt = d_count[e];
    int m0  = blockIdx.x * 128;
    if (m0 >= cnt) return;
    int n0  = blockIdx.y * 128;

    int tid = threadIdx.x;
    if (tid < 128) {
        int m = m0 + tid;
        sPair[tid] = d_list[e * T_TOK + (m < cnt ? m : cnt - 1)];
    }
    __syncthreads();

    int row = tid >> 1;           // 0..127
    int hc  = (tid & 1) * 16;     // k offset in halves

    const __half* aPtr = A  + (size_t)(sPair[row] >> ASHIFT) * KDIM + hc;
    const __half* bPtr = Bw + ((size_t)e * BROWS + n0 + row) * KDIM + hc;

    int warp = tid >> 5;
    int lane = tid & 31;
    int wm = warp & 1;
    int wn = warp >> 1;
    int g  = lane >> 2;
    int tg = lane & 3;

    float acc[4][4][4];
#pragma unroll
    for (int i = 0; i < 4; i++)
#pragma unroll
        for (int j = 0; j < 4; j++)
#pragma unroll
            for (int r = 0; r < 4; r++) acc[i][j][r] = 0.f;

    // prologue: chunk 0 -> regs -> stage 0
    uint4 fa0 = *(const uint4*)(aPtr);
    uint4 fa1 = *(const uint4*)(aPtr + 8);
    uint4 fb0 = *(const uint4*)(bPtr);
    uint4 fb1 = *(const uint4*)(bPtr + 8);
    *(uint4*)&As[0][row][hc + 0] = fa0;
    *(uint4*)&As[0][row][hc + 8] = fa1;
    *(uint4*)&Bs[0][row][hc + 0] = fb0;
    *(uint4*)&Bs[0][row][hc + 8] = fb1;
    __syncthreads();

    const int NCHUNK = KDIM / 32;
    for (int kc = 0; kc < NCHUNK; kc++) {
        int cur = kc & 1;
        int nxt = cur ^ 1;
        bool more = (kc + 1 < NCHUNK);

        // prefetch chunk kc+1 (latency hidden behind compute below)
        if (more) {
            const __half* ap = aPtr + (kc + 1) * 32;
            const __half* bp = bPtr + (kc + 1) * 32;
            fa0 = *(const uint4*)(ap);
            fa1 = *(const uint4*)(ap + 8);
            fb0 = *(const uint4*)(bp);
            fb1 = *(const uint4*)(bp + 8);
        }

        // compute chunk kc from stage cur
#pragma unroll
        for (int s = 0; s < 2; s++) {
            int k0 = s * 16;
            uint32_t afr[4][4], bfr[4][2];
#pragma unroll
            for (int i = 0; i < 4; i++) {
                int R = wm * 64 + i * 16;
                afr[i][0] = *(const uint32_t*)&As[cur][R + g    ][k0 + 2 * tg    ];
                afr[i][1] = *(const uint32_t*)&As[cur][R + g + 8][k0 + 2 * tg    ];
                afr[i][2] = *(const uint32_t*)&As[cur][R + g    ][k0 + 2 * tg + 8];
                afr[i][3] = *(const uint32_t*)&As[cur][R + g + 8][k0 + 2 * tg + 8];
            }
#pragma unroll
            for (int j = 0; j < 4; j++) {
                int N = wn * 32 + j * 8;
                bfr[j][0] = *(const uint32_t*)&Bs[cur][N + g][k0 + 2 * tg    ];
                bfr[j][1] = *(const uint32_t*)&Bs[cur][N + g][k0 + 2 * tg + 8];
            }
#pragma unroll
            for (int i = 0; i < 4; i++)
#pragma unroll
                for (int j = 0; j < 4; j++)
                    mma_f16(acc[i][j], afr[i], bfr[j]);
        }

        // store chunk kc+1 into stage nxt (its last readers synced at iter kc-1)
        if (more) {
            *(uint4*)&As[nxt][row][hc + 0] = fa0;
            *(uint4*)&As[nxt][row][hc + 8] = fa1;
            *(uint4*)&Bs[nxt][row][hc + 0] = fb0;
            *(uint4*)&Bs[nxt][row][hc + 8] = fb1;
        }
        __syncthreads();
    }

    // epilogue
#pragma unroll
    for (int i = 0; i < 4; i++) {
#pragma unroll
        for (int rr = 0; rr < 2; rr++) {
            int mloc = wm * 64 + i * 16 + rr * 8 + g;
            if (m0 + mloc < cnt) {
                int p = sPair[mloc];
                if (MODE == 0) {
                    __half* dst = d_zh + (size_t)p * NF2 + n0 + wn * 32 + tg * 2;
#pragma unroll
                    for (int j = 0; j < 4; j++)
                        *(uint32_t*)(dst + j * 8) =
                            pack2h(acc[i][j][rr * 2 + 0], acc[i][j][rr * 2 + 1]);
                } else {
                    float* dst = d_y + (size_t)p * HDIM + n0 + wn * 32 + tg * 2;
#pragma unroll
                    for (int j = 0; j < 4; j++) {
                        float2 v;
                        v.x = acc[i][j][rr * 2 + 0];
                        v.y = acc[i][j][rr * 2 + 1];
                        *(float2*)(dst + j * 8) = v;
                    }
                }
            }
        }
    }
}

// ---------------- act: silu(g)*u, half in / half out -------------------------
__global__ void act_kernel() {
    int i8 = blockIdx.x * blockDim.x + threadIdx.x;   // over NPAIR*FFND/8
    int p  = i8 >> 9;                                 // / (FFND/8)
    int f8 = i8 & 511;
    if (p >= NPAIR) return;
    const uint4* gp = (const uint4*)(d_zh + (size_t)p * NF2) + f8;
    const uint4* up = (const uint4*)(d_zh + (size_t)p * NF2 + FFND) + f8;
    uint4 gu = *gp, uu = *up, o;
    const __half2* gh = (const __half2*)&gu;
    const __half2* uh = (const __half2*)&uu;
    uint32_t* oh = (uint32_t*)&o;
#pragma unroll
    for (int q = 0; q < 4; q++) {
        float2 gf = __half22float2(gh[q]);
        float2 uf = __half22float2(uh[q]);
        float r0 = gf.x / (1.0f + __expf(-gf.x)) * uf.x;
        float r1 = gf.y / (1.0f + __expf(-gf.y)) * uf.y;
        oh[q] = pack2h(r0, r1);
    }
    ((uint4*)(d_acth + (size_t)p * FFND))[f8] = o;
}

// ---------------- combine: out[t] = w0*y[2t] + w1*y[2t+1] -------------------
__global__ void combine_kernel(float* __restrict__ out) {
    int i4 = blockIdx.x * blockDim.x + threadIdx.x;
    int t  = i4 >> 8;
    int h4 = i4 & 255;
    if (t >= T_TOK) return;
    float w0 = d_wgt[2 * t], w1 = d_wgt[2 * t + 1];
    const float4* y0 = (const float4*)(d_y + (size_t)(2 * t) * HDIM) + h4;
    const float4* y1 = (const float4*)(d_y + (size_t)(2 * t + 1) * HDIM) + h4;
    float4 a = *y0, b = *y1, r;
    r.x = w0 * a.x + w1 * b.x;
    r.y = w0 * a.y + w1 * b.y;
    r.z = w0 * a.z + w1 * b.z;
    r.w = w0 * a.w + w1 * b.w;
    ((float4*)(out + (size_t)t * HDIM))[h4] = r;
}

// ---------------------------------------------------------------------------
extern "C" void kernel_launch(void* const* d_in, const int* in_sizes, int n_in,
                              void* d_out, int out_size) {
    const float* x   = (const float*)d_in[0];
    const float* gw  = (const float*)d_in[1];
    const float* w13 = (const float*)d_in[2];
    const float* w2  = (const float*)d_in[3];
    float* out = (float*)d_out;
    float* rlogits = out + (size_t)T_TOK * HDIM;

    zero_counts_kernel<<<1, 32>>>();
    router_kernel<<<T_TOK / 8, 256>>>(x, gw, rlogits);
    convert_x_kernel<<<(T_TOK * HDIM / 8 + 255) / 256, 256>>>(x);
    // 96M floats / 8 per thread / 256 per block = 49152 blocks
    convert_w_kernel<<<49152, 256>>>(w13, w2);

    // GEMM1 (fp16): z_h = x_h . w13_h[e]^T, K=1024
    dim3 g1(T_TOK / 128, NF2 / 128, NE);      // (16, 64, 8)
    gemm_f16_kernel<HDIM, NF2, 0><<<g1, 256>>>();

    act_kernel<<<(NPAIR * FFND / 8) / 256, 256>>>();

    // GEMM2 (fp16): y = act_h . w2_h[e]^T, K=4096
    dim3 g2(T_TOK / 128, HDIM / 128, NE);     // (16, 8, 8)
    gemm_f16_kernel<FFND, HDIM, 1><<<g2, 256>>>();

    combine_kernel<<<(T_TOK * HDIM / 4) / 256, 256>>>(out);
}